// round 1
// baseline (speedup 1.0000x reference)
#include <cuda_runtime.h>
#include <cuda_bf16.h>

// Problem constants (fixed shapes per reference setup_inputs)
#define BQ    8      // batch
#define BSZ   16     // block_size
#define MAXB  128    // max blocks per seq
#define NH    8      // kv heads
#define HD    128    // head dim
#define NTOT  2048   // total physical blocks
// float4 counts
#define HALF4 (NTOT * NH * BSZ * (HD / 4))   // 8,388,608 float4 per cache
#define N4    (2 * HALF4)                    // 16,777,216 float4 total output

// Inverse map: physical block -> (b * MAXB + slot), or -1 if untouched.
__device__ int g_owner[NTOT];

__global__ void init_owner_kernel() {
    int i = blockIdx.x * blockDim.x + threadIdx.x;
    if (i < NTOT) g_owner[i] = -1;
}

// One thread per (b, slot). Reproduces the reference's tail-pop free-list
// allocation, computes the updated block-table entry, and marks ownership
// for every slot whose block receives at least one new token.
__global__ void build_owner_kernel(const int* __restrict__ seq_lens,
                                   const int* __restrict__ input_len,
                                   const int* __restrict__ block_tables,
                                   const int* __restrict__ free_blocks,
                                   int num_free) {
    int tid  = blockIdx.x * blockDim.x + threadIdx.x;
    int b    = tid / MAXB;
    int slot = tid % MAXB;
    if (b >= BQ) return;

    int sl = seq_lens[b];
    int il = input_len[b];
    int old_nb = (sl + BSZ - 1) / BSZ;
    int new_nb = (sl + il + BSZ - 1) / BSZ;

    // cumulative allocation over sequences 0..b (B is tiny; loop is cheap)
    int cum = 0;
    for (int j = 0; j <= b; j++) {
        int s = seq_lens[j], l = input_len[j];
        cum += (s + l + BSZ - 1) / BSZ - (s + BSZ - 1) / BSZ;
    }
    int start = num_free - cum;

    int bt;
    if (slot >= old_nb && slot < new_nb) {
        int fi = start + (slot - old_nb);
        fi = max(0, min(fi, num_free - 1));
        bt = free_blocks[fi];
    } else {
        bt = block_tables[b * MAXB + slot];
    }

    if (il > 0) {
        int first = sl / BSZ;
        int last  = (sl + il - 1) / BSZ;
        if (slot >= first && slot <= last) {
            g_owner[bt] = b * MAXB + slot;
        }
    }
}

// One float4 per thread; one warp covers exactly one (blk, h, off) row of
// 128 floats, so the source-select branch is warp-uniform. Every output
// element is written exactly once; scattered rows read the packed K/V
// states instead of the cache (no double traffic).
__global__ void __launch_bounds__(256, 8)
scatter_copy_kernel(const float4* __restrict__ keys,
                    const float4* __restrict__ vals,
                    const float4* __restrict__ kc,
                    const float4* __restrict__ vc,
                    const int* __restrict__ seq_lens,
                    const int* __restrict__ input_len,
                    const int* __restrict__ cu_seqlens,
                    float4* __restrict__ out) {
    int i = blockIdx.x * blockDim.x + threadIdx.x;
    if (i >= N4) return;

    // decode [c:1][blk:11][h:3][off:4][d4:5]
    int d4  = i & 31;
    int r   = i >> 5;
    int off = r & 15;  r >>= 4;
    int h   = r & 7;   r >>= 3;
    int blk = r & (NTOT - 1);
    int c   = r >> 11;                 // 0 = K, 1 = V

    int owner = g_owner[blk];

    float4 v;
    bool from_new = false;
    int src4 = 0;
    if (owner >= 0) {
        int b    = owner >> 7;         // / MAXB
        int slot = owner & (MAXB - 1);
        int pos  = slot * BSZ + off;   // absolute position in sequence
        int t    = pos - seq_lens[b];  // new-token index
        if (t >= 0 && t < input_len[b]) {
            int tok = cu_seqlens[b] + t;
            src4 = (tok * NH + h) * (HD / 4) + d4;
            from_new = true;
        }
    }

    int ci = i & (HALF4 - 1);          // index within one cache tensor
    if (from_new) {
        v = c ? vals[src4] : keys[src4];
    } else {
        v = c ? vc[ci] : kc[ci];
    }
    out[i] = v;
}

extern "C" void kernel_launch(void* const* d_in, const int* in_sizes, int n_in,
                              void* d_out, int out_size) {
    // metadata order:
    // 0: layer_idx (unused)
    // 1: key_states   [B*L, H, D] f32
    // 2: value_states [B*L, H, D] f32
    // 3: input_len    [B] i32
    // 4: cu_seqlens   [B+1] i32
    // 5: k_cache      [TOTAL, H, BS, D] f32
    // 6: v_cache      [TOTAL, H, BS, D] f32
    // 7: block_tables [B, MAXB] i32
    // 8: seq_lens     [B] i32
    // 9: free_blocks  [TOTAL] i32
    const float4* keys        = (const float4*)d_in[1];
    const float4* vals        = (const float4*)d_in[2];
    const int*    input_len   = (const int*)d_in[3];
    const int*    cu_seqlens  = (const int*)d_in[4];
    const float4* kc          = (const float4*)d_in[5];
    const float4* vc          = (const float4*)d_in[6];
    const int*    block_tbl   = (const int*)d_in[7];
    const int*    seq_lens    = (const int*)d_in[8];
    const int*    free_blocks = (const int*)d_in[9];
    int num_free = in_sizes[9];

    float4* out = (float4*)d_out;

    init_owner_kernel<<<(NTOT + 255) / 256, 256>>>();
    build_owner_kernel<<<(BQ * MAXB + 255) / 256, 256>>>(
        seq_lens, input_len, block_tbl, free_blocks, num_free);
    scatter_copy_kernel<<<N4 / 256, 256>>>(
        keys, vals, kc, vc, seq_lens, input_len, cu_seqlens, out);
}

// round 2
// speedup vs baseline: 1.1507x; 1.1507x over previous
#include <cuda_runtime.h>
#include <cuda_bf16.h>

// Problem constants (fixed shapes per reference setup_inputs)
#define BQ    8      // batch
#define BSZ   16     // block_size
#define MAXB  128    // max blocks per seq
#define NH    8      // kv heads
#define HD    128    // head dim
#define NTOT  2048   // total physical blocks
// float4 counts
#define HALF4 (NTOT * NH * BSZ * (HD / 4))   // 8,388,608 float4 per cache tensor
#define N4    (2 * HALF4)                    // 16,777,216 float4 total output

// Inverse map: physical block -> (b * MAXB + slot), or -1 if untouched.
__device__ int g_owner[NTOT];

// Single-block fused prologue: init the owner map, then reproduce the
// reference's tail-pop free-list allocation and mark ownership for every
// slot whose block receives at least one new token. One launch instead of two.
__global__ void __launch_bounds__(1024, 1)
prologue_kernel(const int* __restrict__ seq_lens,
                const int* __restrict__ input_len,
                const int* __restrict__ block_tables,
                const int* __restrict__ free_blocks,
                int num_free) {
    int tid = threadIdx.x;            // 0..1023
    g_owner[tid]        = -1;
    g_owner[tid + 1024] = -1;
    __syncthreads();

    // One thread per (b, slot): BQ * MAXB = 1024 exactly.
    int b    = tid >> 7;              // / MAXB
    int slot = tid & (MAXB - 1);

    int sl = seq_lens[b];
    int il = input_len[b];
    int old_nb = (sl + BSZ - 1) / BSZ;
    int new_nb = (sl + il + BSZ - 1) / BSZ;

    // cumulative allocation over sequences 0..b (B tiny; loop is cheap)
    int cum = 0;
    for (int j = 0; j <= b; j++) {
        int s = seq_lens[j], l = input_len[j];
        cum += (s + l + BSZ - 1) / BSZ - (s + BSZ - 1) / BSZ;
    }
    int start = num_free - cum;

    // (block-table value for this slot; only the new-token range matters
    //  for ownership marking, but compute exactly as the reference does)
    int bt;
    if (slot >= old_nb && slot < new_nb) {
        int fi = start + (slot - old_nb);
        fi = max(0, min(fi, num_free - 1));
        bt = free_blocks[fi];
    } else {
        bt = block_tables[b * MAXB + slot];
    }

    if (il > 0) {
        int first = sl / BSZ;
        int last  = (sl + il - 1) / BSZ;
        if (slot >= first && slot <= last) {
            g_owner[bt] = b * MAXB + slot;
        }
    }
}

// One thread handles the K float4 at index i AND its V twin at i+HALF4:
// identical decode, identical source index, two independent 16B loads and
// two 16B stores (MLP=2). A warp covers exactly one (blk, h, off) row of
// 128 floats in each tensor, so the source-select branch is warp-uniform
// and every access is a fully-coalesced 128-bit op. Streaming hints keep
// the 512MB one-pass stream from thrashing L2.
__global__ void __launch_bounds__(256, 8)
scatter_copy_kernel(const float4* __restrict__ keys,
                    const float4* __restrict__ vals,
                    const float4* __restrict__ kc,
                    const float4* __restrict__ vc,
                    const int* __restrict__ seq_lens,
                    const int* __restrict__ input_len,
                    const int* __restrict__ cu_seqlens,
                    float4* __restrict__ out) {
    int i = blockIdx.x * blockDim.x + threadIdx.x;   // 0 .. HALF4-1

    // decode [blk:11][h:3][off:4][d4:5]
    int d4  = i & 31;
    int r   = i >> 5;
    int off = r & 15;  r >>= 4;
    int h   = r & 7;
    int blk = r >> 3;                 // < NTOT

    int owner = g_owner[blk];

    float4 kv, vv;
    bool from_new = false;
    if (owner >= 0) {
        int b    = owner >> 7;        // / MAXB
        int slot = owner & (MAXB - 1);
        int pos  = slot * BSZ + off;  // absolute position in sequence
        int t    = pos - seq_lens[b]; // new-token index
        if (t >= 0 && t < input_len[b]) {
            int tok  = cu_seqlens[b] + t;
            int src4 = (tok * NH + h) * (HD / 4) + d4;
            kv = __ldcs(keys + src4);
            vv = __ldcs(vals + src4);
            from_new = true;
        }
    }
    if (!from_new) {
        kv = __ldcs(kc + i);
        vv = __ldcs(vc + i);
    }

    __stcs(out + i,         kv);
    __stcs(out + i + HALF4, vv);
}

extern "C" void kernel_launch(void* const* d_in, const int* in_sizes, int n_in,
                              void* d_out, int out_size) {
    // metadata order:
    // 0: layer_idx (unused)
    // 1: key_states   [B*L, H, D] f32
    // 2: value_states [B*L, H, D] f32
    // 3: input_len    [B] i32
    // 4: cu_seqlens   [B+1] i32
    // 5: k_cache      [TOTAL, H, BS, D] f32
    // 6: v_cache      [TOTAL, H, BS, D] f32
    // 7: block_tables [B, MAXB] i32
    // 8: seq_lens     [B] i32
    // 9: free_blocks  [TOTAL] i32
    const float4* keys        = (const float4*)d_in[1];
    const float4* vals        = (const float4*)d_in[2];
    const int*    input_len   = (const int*)d_in[3];
    const int*    cu_seqlens  = (const int*)d_in[4];
    const float4* kc          = (const float4*)d_in[5];
    const float4* vc          = (const float4*)d_in[6];
    const int*    block_tbl   = (const int*)d_in[7];
    const int*    seq_lens    = (const int*)d_in[8];
    const int*    free_blocks = (const int*)d_in[9];
    int num_free = in_sizes[9];

    float4* out = (float4*)d_out;

    prologue_kernel<<<1, 1024>>>(seq_lens, input_len, block_tbl,
                                 free_blocks, num_free);
    scatter_copy_kernel<<<HALF4 / 256, 256>>>(
        keys, vals, kc, vc, seq_lens, input_len, cu_seqlens, out);
}